// round 6
// baseline (speedup 1.0000x reference)
#include <cuda_runtime.h>
#include <cstdint>

// Problem constants
#define DIMN   256      // d and e dimension
#define BATCH  256
#define KSEQ   2048
#define NCOLS  (KSEQ * BATCH)   // 524288 columns, column n = k*256 + b, contiguous 256 floats each

// Main-kernel tiling
#define KC        32            // k-chunk
#define NTILE     64            // columns per CTA
#define WS_STRIDE 260           // floats per k-row of W smem (padded; 260*4 % 16 == 0)
#define ES_STRIDE 68            // floats per k-row of E smem (64 + swizzle pad)

// qc[b][d] = query@Wq^T + bq + bref  (bref folded in)
__device__ float g_qc[BATCH * DIMN];

// ---------- helpers ----------
__device__ __forceinline__ unsigned long long dup_f32x2(float x) {
    unsigned long long r;
    asm("mov.b64 %0, {%1, %1};" : "=l"(r) : "f"(x));
    return r;
}
__device__ __forceinline__ void fma_f32x2(unsigned long long &acc,
                                          unsigned long long a,
                                          unsigned long long b) {
    asm("fma.rn.f32x2 %0, %1, %2, %0;" : "+l"(acc) : "l"(a), "l"(b));
}
__device__ __forceinline__ float2 ull_to_f2(unsigned long long x) {
    float2 r;
    asm("mov.b64 {%0, %1}, %2;" : "=f"(r.x), "=f"(r.y) : "l"(x));
    return r;
}
__device__ __forceinline__ float tanh_fast(float x) {
    float r;
    asm("tanh.approx.f32 %0, %1;" : "=f"(r) : "f"(x));
    return r;
}

// ---------- kernel 1: qc precompute ----------
__global__ void __launch_bounds__(256) qc_kernel(const float* __restrict__ query,
                                                 const float* __restrict__ Wq,
                                                 const float* __restrict__ bq,
                                                 const float* __restrict__ bref) {
    const int b = blockIdx.x;
    const int d = threadIdx.x;
    __shared__ float qrow[DIMN];
    qrow[d] = query[b * DIMN + d];
    __syncthreads();

    const float4* w4 = reinterpret_cast<const float4*>(Wq + d * DIMN);
    float acc = 0.0f;
#pragma unroll 8
    for (int e4 = 0; e4 < DIMN / 4; e4++) {
        float4 w = w4[e4];
        const float4 q = *reinterpret_cast<const float4*>(qrow + e4 * 4);  // broadcast
        acc = fmaf(w.x, q.x, acc);
        acc = fmaf(w.y, q.y, acc);
        acc = fmaf(w.z, q.z, acc);
        acc = fmaf(w.w, q.w, acc);
    }
    g_qc[b * DIMN + d] = acc + bq[d] + bref[d];
}

// ---------- kernel 2: fused GEMM + tanh attention scoring ----------
// CTA: 256 threads = (tidy 0..31 over M in groups of 8) x (tidx 0..7 over N in groups of 8)
// acc pairs over N (f32x2 lanes = columns n, n+1)
__global__ void __launch_bounds__(256) attn_main(const float* __restrict__ enc,
                                                 const float* __restrict__ Wref,
                                                 const float* __restrict__ v,
                                                 float* __restrict__ out) {
    __shared__ float Ws[KC * WS_STRIDE];  // Ws[k][m] = Wref[m][k0+k]  (transposed)
    __shared__ float Es[KC * ES_STRIDE];  // Es[k][swz(n)] = enc[colBase+n][k0+k]

    const int tid  = threadIdx.x;
    const int tidy = tid >> 3;   // 0..31  (m = 8*tidy + i)
    const int tidx = tid & 7;    // 0..7   (n = 8*tidx + j)
    const int colBase = blockIdx.x * NTILE;

    // ---- global-load assignments ----
    // W fill: thread loads float4 at row (tidy + 32r), k-quad tidx  (coalesced: 4 rows x 128B per warp)
    // E fill: thread ncl = tid>>2 (column), eq = tid&3 (8-float k-segment)
    const int ncl = tid >> 2;
    const int eq  = tid & 3;
    const float* wg_base = Wref + tidy * DIMN + tidx * 4;
    const float* eg_base = enc + (size_t)(colBase + ncl) * DIMN + eq * 8;

    float4 wst[8];
    float4 est[2];

    // prefetch chunk 0
#pragma unroll
    for (int r = 0; r < 8; r++)
        wst[r] = *reinterpret_cast<const float4*>(wg_base + (32 * r) * DIMN);
    est[0] = *reinterpret_cast<const float4*>(eg_base);
    est[1] = *reinterpret_cast<const float4*>(eg_base + 4);

    unsigned long long acc[32];  // acc[i*4 + jp] : m = 8*tidy+i, n pair = (8*tidx+2jp, +1)
#pragma unroll
    for (int i = 0; i < 32; i++) acc[i] = 0ull;

    // compute-read base pointers (constant across chunks)
    const float4*      wsp = reinterpret_cast<const float4*>(Ws + 8 * tidy);             // + k*65
    const int          esw = 8 * tidx + ((tidx >> 2) << 2);                              // swizzled n offset
    const ulonglong2*  esp = reinterpret_cast<const ulonglong2*>(Es + esw);              // + k*17

    // E-store swizzle index for fill
    const int sn = ncl + ((ncl >> 5) << 2);

    for (int c = 0; c < DIMN / KC; c++) {
        __syncthreads();
        // stage registers -> smem (W transposed)
#pragma unroll
        for (int r = 0; r < 8; r++) {
            const int m = tidy + 32 * r;
            float4 w = wst[r];
            Ws[(tidx * 4 + 0) * WS_STRIDE + m] = w.x;
            Ws[(tidx * 4 + 1) * WS_STRIDE + m] = w.y;
            Ws[(tidx * 4 + 2) * WS_STRIDE + m] = w.z;
            Ws[(tidx * 4 + 3) * WS_STRIDE + m] = w.w;
        }
#pragma unroll
        for (int q = 0; q < 2; q++) {
            const int kl = eq * 8 + q * 4;
            float4 e = est[q];
            Es[(kl + 0) * ES_STRIDE + sn] = e.x;
            Es[(kl + 1) * ES_STRIDE + sn] = e.y;
            Es[(kl + 2) * ES_STRIDE + sn] = e.z;
            Es[(kl + 3) * ES_STRIDE + sn] = e.w;
        }
        __syncthreads();

        // prefetch next chunk while computing this one
        if (c < DIMN / KC - 1) {
            const int k0n = (c + 1) * KC;
#pragma unroll
            for (int r = 0; r < 8; r++)
                wst[r] = *reinterpret_cast<const float4*>(wg_base + (32 * r) * DIMN + k0n);
            est[0] = *reinterpret_cast<const float4*>(eg_base + k0n);
            est[1] = *reinterpret_cast<const float4*>(eg_base + k0n + 4);
        }

        // ---- main FFMA2 loop over KC k-steps ----
#pragma unroll
        for (int k = 0; k < KC; k++) {
            const float4 w0 = wsp[k * (WS_STRIDE / 4) + 0];
            const float4 w1 = wsp[k * (WS_STRIDE / 4) + 1];
            const ulonglong2 eA = esp[k * (ES_STRIDE / 4) + 0];  // b0 = (n0,n1), b1 = (n2,n3)
            const ulonglong2 eB = esp[k * (ES_STRIDE / 4) + 1];  // b2 = (n4,n5), b3 = (n6,n7)
            unsigned long long a;
            a = dup_f32x2(w0.x);
            fma_f32x2(acc[0], a, eA.x);  fma_f32x2(acc[1], a, eA.y);
            fma_f32x2(acc[2], a, eB.x);  fma_f32x2(acc[3], a, eB.y);
            a = dup_f32x2(w0.y);
            fma_f32x2(acc[4], a, eA.x);  fma_f32x2(acc[5], a, eA.y);
            fma_f32x2(acc[6], a, eB.x);  fma_f32x2(acc[7], a, eB.y);
            a = dup_f32x2(w0.z);
            fma_f32x2(acc[8], a, eA.x);  fma_f32x2(acc[9], a, eA.y);
            fma_f32x2(acc[10], a, eB.x); fma_f32x2(acc[11], a, eB.y);
            a = dup_f32x2(w0.w);
            fma_f32x2(acc[12], a, eA.x); fma_f32x2(acc[13], a, eA.y);
            fma_f32x2(acc[14], a, eB.x); fma_f32x2(acc[15], a, eB.y);
            a = dup_f32x2(w1.x);
            fma_f32x2(acc[16], a, eA.x); fma_f32x2(acc[17], a, eA.y);
            fma_f32x2(acc[18], a, eB.x); fma_f32x2(acc[19], a, eB.y);
            a = dup_f32x2(w1.y);
            fma_f32x2(acc[20], a, eA.x); fma_f32x2(acc[21], a, eA.y);
            fma_f32x2(acc[22], a, eB.x); fma_f32x2(acc[23], a, eB.y);
            a = dup_f32x2(w1.z);
            fma_f32x2(acc[24], a, eA.x); fma_f32x2(acc[25], a, eA.y);
            fma_f32x2(acc[26], a, eB.x); fma_f32x2(acc[27], a, eB.y);
            a = dup_f32x2(w1.w);
            fma_f32x2(acc[28], a, eA.x); fma_f32x2(acc[29], a, eA.y);
            fma_f32x2(acc[30], a, eB.x); fma_f32x2(acc[31], a, eB.y);
        }
    }

    // ---- epilogue: tanh, v-weighted reduce over m, cross-thread reduce over tidy ----
    float vv[8];
    {
        const float4 va = *reinterpret_cast<const float4*>(v + 8 * tidy);
        const float4 vb = *reinterpret_cast<const float4*>(v + 8 * tidy + 4);
        vv[0] = va.x; vv[1] = va.y; vv[2] = va.z; vv[3] = va.w;
        vv[4] = vb.x; vv[5] = vb.y; vv[6] = vb.z; vv[7] = vb.w;
    }

    float sred[8];
#pragma unroll
    for (int jp = 0; jp < 4; jp++) {
        const int n0 = colBase + 8 * tidx + 2 * jp;
        const int b0 = n0 & 255;
        const int b1 = (n0 + 1) & 255;
        float qa[8], qb[8];
        {
            const float4 q0a = *reinterpret_cast<const float4*>(g_qc + b0 * DIMN + 8 * tidy);
            const float4 q0b = *reinterpret_cast<const float4*>(g_qc + b0 * DIMN + 8 * tidy + 4);
            const float4 q1a = *reinterpret_cast<const float4*>(g_qc + b1 * DIMN + 8 * tidy);
            const float4 q1b = *reinterpret_cast<const float4*>(g_qc + b1 * DIMN + 8 * tidy + 4);
            qa[0]=q0a.x; qa[1]=q0a.y; qa[2]=q0a.z; qa[3]=q0a.w;
            qa[4]=q0b.x; qa[5]=q0b.y; qa[6]=q0b.z; qa[7]=q0b.w;
            qb[0]=q1a.x; qb[1]=q1a.y; qb[2]=q1a.z; qb[3]=q1a.w;
            qb[4]=q1b.x; qb[5]=q1b.y; qb[6]=q1b.z; qb[7]=q1b.w;
        }
        float s0 = 0.0f, s1 = 0.0f;
#pragma unroll
        for (int i = 0; i < 8; i++) {
            const float2 y = ull_to_f2(acc[i * 4 + jp]);
            s0 = fmaf(vv[i], tanh_fast(y.x + qa[i]), s0);
            s1 = fmaf(vv[i], tanh_fast(y.y + qb[i]), s1);
        }
        sred[2 * jp]     = s0;
        sred[2 * jp + 1] = s1;
    }

    // reuse Es as the reduction buffer (red[32][64]); all compute reads of Es are done
    __syncthreads();
    float* red = Es;
#pragma unroll
    for (int j = 0; j < 8; j++)
        red[tidy * 64 + 8 * tidx + j] = sred[j];
    __syncthreads();

    if (tid < 64) {
        float u = 0.0f;
#pragma unroll 8
        for (int r = 0; r < 32; r++)
            u += red[r * 64 + tid];
        const int n = colBase + tid;
        const int b = n & 255;
        const int k = n >> 8;
        out[b * KSEQ + k] = 10.0f * tanhf(u);   // accurate outer tanh
    }
}

extern "C" void kernel_launch(void* const* d_in, const int* in_sizes, int n_in,
                              void* d_out, int out_size) {
    const float* enc   = (const float*)d_in[0];  // (2048, 256, 256)
    const float* query = (const float*)d_in[1];  // (256, 256)
    const float* Wq    = (const float*)d_in[2];  // (256, 256)
    const float* bq    = (const float*)d_in[3];  // (256,)
    const float* Wref  = (const float*)d_in[4];  // (256, 256)
    const float* bref  = (const float*)d_in[5];  // (256,)
    const float* v     = (const float*)d_in[6];  // (256,)
    float* out = (float*)d_out;                  // (256, 2048)

    qc_kernel<<<BATCH, DIMN>>>(query, Wq, bq, bref);
    attn_main<<<NCOLS / NTILE, 256>>>(enc, Wref, v, out);
}

// round 9
// speedup vs baseline: 2.0926x; 2.0926x over previous
#include <cuda_runtime.h>
#include <cstdint>
#include <cstddef>

// ---------------- problem constants ----------------
#define DIM    256
#define BATCH  256
#define KSEQ   2048
#define KC     32                    // K-chunk (e dimension)
#define NCHUNK 8
#define ROWS_CTA 128                 // output columns (n) per CTA: 32 b x 4 k
#define GRID   ((KSEQ * BATCH) / ROWS_CTA)   // 4096

// ---------------- smem layout (floats) ----------------
#define LDA      36                  // padded row stride (36*4=144 B, 16B-aligned, CF banks)
#define ASTRIDE  (128 * LDA)         // 4608 floats per A buffer
#define B_OFF    (2 * ASTRIDE)       // 9216: B buffers start
#define BSTRIDE  (256 * LDA)         // 9216 floats per B buffer
#define SMEM_FLOATS (B_OFF + 2 * BSTRIDE)    // 27648 floats
#define SMEM_TOTAL  (SMEM_FLOATS * 4)        // 110592 B
// epilogue overlays (after mainloop):
#define QS_LD    260                 // qc tile stride (32 x 260 floats, fits in A region)
#define RED_OFF  B_OFF               // reduction buffer 128 x 5 floats (in B region)

__device__ float g_qc[BATCH * DIM];  // qc[b][d] = query@Wq^T + bq + bref

// ---------------- helpers ----------------
__device__ __forceinline__ uint32_t smem_u32(const void* p) {
    uint32_t a;
    asm("{ .reg .u64 t; cvta.to.shared.u64 t, %1; cvt.u32.u64 %0, t; }" : "=r"(a) : "l"(p));
    return a;
}
__device__ __forceinline__ uint32_t cvt_tf32(float x) {
    uint32_t r;
    asm("cvt.rna.tf32.f32 %0, %1;" : "=r"(r) : "f"(x));
    return r;
}
__device__ __forceinline__ float tanh_fast(float x) {
    float r;
    asm("tanh.approx.f32 %0, %1;" : "=f"(r) : "f"(x));
    return r;
}
__device__ __forceinline__ void cp_async16(uint32_t saddr, const void* gaddr) {
    asm volatile("cp.async.cg.shared.global [%0], [%1], 16;"
                 :: "r"(saddr), "l"(gaddr) : "memory");
}
__device__ __forceinline__ void mma_tf32(float* d, const uint32_t* a, const uint32_t* b) {
    asm volatile(
        "mma.sync.aligned.m16n8k8.row.col.f32.tf32.tf32.f32 "
        "{%0,%1,%2,%3}, {%4,%5,%6,%7}, {%8,%9}, {%0,%1,%2,%3};"
        : "+f"(d[0]), "+f"(d[1]), "+f"(d[2]), "+f"(d[3])
        : "r"(a[0]), "r"(a[1]), "r"(a[2]), "r"(a[3]), "r"(b[0]), "r"(b[1]));
}

// ---------------- kernel 1: qc precompute ----------------
__global__ void __launch_bounds__(256) qc_kernel(const float* __restrict__ query,
                                                 const float* __restrict__ Wq,
                                                 const float* __restrict__ bq,
                                                 const float* __restrict__ bref) {
    const int b = blockIdx.x;
    const int d = threadIdx.x;
    __shared__ float qrow[DIM];
    qrow[d] = query[b * DIM + d];
    __syncthreads();

    const float4* w4 = reinterpret_cast<const float4*>(Wq + d * DIM);
    float acc = 0.0f;
#pragma unroll 8
    for (int e4 = 0; e4 < DIM / 4; e4++) {
        float4 w = w4[e4];
        const float4 q = *reinterpret_cast<const float4*>(qrow + e4 * 4);
        acc = fmaf(w.x, q.x, acc);
        acc = fmaf(w.y, q.y, acc);
        acc = fmaf(w.z, q.z, acc);
        acc = fmaf(w.w, q.w, acc);
    }
    g_qc[b * DIM + d] = acc + bq[d] + bref[d];
}

// ---------------- kernel 2: mma.sync tf32 GEMM + tanh epilogue ----------------
// D[n,d] with n-tile = 128 rows: row r -> b = SB + (r&31), k = SK + (r>>5).
// 8 warps: wn = warp>>2 (n 64-half), wd = warp&3 (d 64-slice). Warp tile 64x64.
__global__ void __launch_bounds__(256, 1) attn_main(const float* __restrict__ enc,
                                                    const float* __restrict__ Wref,
                                                    const float* __restrict__ v,
                                                    float* __restrict__ out) {
    extern __shared__ float sm[];
    const uint32_t sbase = smem_u32(sm);
    const int tid  = threadIdx.x;
    const int lane = tid & 31;
    const int warp = tid >> 5;
    const int g = lane >> 2;          // group id (row within 8)
    const int t = lane & 3;           // thread-in-group (k col)
    const int wn = warp >> 2;         // 0..1
    const int wd = warp & 3;          // 0..3
    const int SB = (blockIdx.x & 7) * 32;
    const int SK = (blockIdx.x >> 3) * 4;

    // ---- cp.async copy mapping ----
    // A: 128 rows x 32 floats; thread t: row = tid>>1, 4x16B at col (tid&1)*16
    // B: 256 rows x 32 floats; thread t: row = tid, 8x16B (full row)
    const int rowA = tid >> 1;
    const int nA = (SK + (rowA >> 5)) * 256 + SB + (rowA & 31);
    const float* gA = enc + (size_t)nA * DIM + (tid & 1) * 16;
    const float* gB = Wref + (size_t)tid * DIM;
    const uint32_t sA = sbase + (uint32_t)(rowA * LDA + (tid & 1) * 16) * 4u;
    const uint32_t sB = sbase + (uint32_t)(B_OFF + tid * LDA) * 4u;

    float acc[4][8][4];
#pragma unroll
    for (int m = 0; m < 4; m++)
#pragma unroll
        for (int j = 0; j < 8; j++)
#pragma unroll
            for (int c4 = 0; c4 < 4; c4++) acc[m][j][c4] = 0.0f;

    // prologue: issue chunk 0
    {
        const int k0 = 0;
#pragma unroll
        for (int i = 0; i < 4; i++) cp_async16(sA + i * 16, gA + k0 + i * 4);
#pragma unroll
        for (int i = 0; i < 8; i++) cp_async16(sB + i * 16, gB + k0 + i * 4);
        asm volatile("cp.async.commit_group;" ::: "memory");
    }

    for (int c = 0; c < NCHUNK; c++) {
        if (c + 1 < NCHUNK) {   // issue next chunk into other buffer
            const int k0 = (c + 1) * KC;
            const uint32_t boff = (uint32_t)((c + 1) & 1);
            const uint32_t sa = sA + boff * (ASTRIDE * 4u);
            const uint32_t sb2 = sB + boff * (BSTRIDE * 4u);
#pragma unroll
            for (int i = 0; i < 4; i++) cp_async16(sa + i * 16, gA + k0 + i * 4);
#pragma unroll
            for (int i = 0; i < 8; i++) cp_async16(sb2 + i * 16, gB + k0 + i * 4);
            asm volatile("cp.async.commit_group;" ::: "memory");
            asm volatile("cp.async.wait_group 1;" ::: "memory");
        } else {
            asm volatile("cp.async.wait_group 0;" ::: "memory");
        }
        __syncthreads();

        const float* A = sm + (c & 1) * ASTRIDE + (wn * 64 + g) * LDA;
        const float* B = sm + B_OFF + (c & 1) * BSTRIDE + (wd * 64 + g) * LDA;

#pragma unroll
        for (int s = 0; s < 4; s++) {      // 4 k8-steps per 32-chunk
            const int kc = s * 8 + t;
            uint32_t af[4][4], bf[8][2];
#pragma unroll
            for (int m = 0; m < 4; m++) {
                af[m][0] = cvt_tf32(A[(16 * m) * LDA + kc]);
                af[m][1] = cvt_tf32(A[(16 * m + 8) * LDA + kc]);
                af[m][2] = cvt_tf32(A[(16 * m) * LDA + kc + 4]);
                af[m][3] = cvt_tf32(A[(16 * m + 8) * LDA + kc + 4]);
            }
#pragma unroll
            for (int j = 0; j < 8; j++) {
                bf[j][0] = cvt_tf32(B[(8 * j) * LDA + kc]);
                bf[j][1] = cvt_tf32(B[(8 * j) * LDA + kc + 4]);
            }
#pragma unroll
            for (int m = 0; m < 4; m++)
#pragma unroll
                for (int j = 0; j < 8; j++)
                    mma_tf32(acc[m][j], af[m], bf[j]);
        }
        __syncthreads();   // before next iteration's cp.async overwrites
    }

    // ---- epilogue ----
    // stage qc tile (32 b x 256 d) into smem (overlays A buffers)
    {
        const int r = tid >> 3, seg = (tid & 7) * 32;
        const float* src = g_qc + (size_t)(SB + r) * DIM + seg;
        float* dst = sm + r * QS_LD + seg;
#pragma unroll
        for (int i = 0; i < 8; i++)
            *reinterpret_cast<float4*>(dst + 4 * i) =
                *reinterpret_cast<const float4*>(src + 4 * i);
    }
    __syncthreads();

    float vv[8][2];
#pragma unroll
    for (int j = 0; j < 8; j++) {
        const int d = wd * 64 + 8 * j + 2 * t;
        vv[j][0] = v[d];
        vv[j][1] = v[d + 1];
    }

    float part[4][2];
#pragma unroll
    for (int m = 0; m < 4; m++) {
#pragma unroll
        for (int h = 0; h < 2; h++) {
            const int row = wn * 64 + 16 * m + 8 * h + g;
            const float* q = sm + (row & 31) * QS_LD + wd * 64 + 2 * t;
            float p = 0.0f;
#pragma unroll
            for (int j = 0; j < 8; j++) {
                p = fmaf(vv[j][0], tanh_fast(acc[m][j][2 * h]     + q[8 * j]),     p);
                p = fmaf(vv[j][1], tanh_fast(acc[m][j][2 * h + 1] + q[8 * j + 1]), p);
            }
            // quad (t) reduction: lanes 4g..4g+3 share the same row
            p += __shfl_xor_sync(0xffffffffu, p, 1);
            p += __shfl_xor_sync(0xffffffffu, p, 2);
            part[m][h] = p;
        }
    }

    if (t == 0) {
#pragma unroll
        for (int m = 0; m < 4; m++)
#pragma unroll
            for (int h = 0; h < 2; h++) {
                const int row = wn * 64 + 16 * m + 8 * h + g;
                sm[RED_OFF + row * 5 + wd] = part[m][h];
            }
    }
    __syncthreads();

    if (tid < 128) {
        const float u = sm[RED_OFF + tid * 5]     + sm[RED_OFF + tid * 5 + 1]
                      + sm[RED_OFF + tid * 5 + 2] + sm[RED_OFF + tid * 5 + 3];
        out[(size_t)(SB + (tid & 31)) * KSEQ + SK + (tid >> 5)] = 10.0f * tanhf(u);
    }
}

extern "C" void kernel_launch(void* const* d_in, const int* in_sizes, int n_in,
                              void* d_out, int out_size) {
    const float* enc   = (const float*)d_in[0];  // (2048, 256, 256)
    const float* query = (const float*)d_in[1];  // (256, 256)
    const float* Wq    = (const float*)d_in[2];  // (256, 256)
    const float* bq    = (const float*)d_in[3];  // (256,)
    const float* Wref  = (const float*)d_in[4];  // (256, 256)
    const float* bref  = (const float*)d_in[5];  // (256,)
    const float* v     = (const float*)d_in[6];  // (256,)
    float* out = (float*)d_out;                  // (256, 2048)

    cudaFuncSetAttribute(attn_main, cudaFuncAttributeMaxDynamicSharedMemorySize, SMEM_TOTAL);

    qc_kernel<<<BATCH, DIM>>>(query, Wq, bq, bref);
    attn_main<<<GRID, 256, SMEM_TOTAL>>>(enc, Wref, v, out);
}

// round 10
// speedup vs baseline: 2.5752x; 1.2306x over previous
#include <cuda_runtime.h>
#include <cstdint>
#include <cstddef>

// ---------------- problem constants ----------------
#define DIM    256
#define BATCH  256
#define KSEQ   2048
#define KC     32                    // K-chunk (e dimension)
#define NCHUNK 8
#define ROWS_CTA 128                 // output columns (n) per CTA: 32 b x 4 k
#define GRID   ((KSEQ * BATCH) / ROWS_CTA)   // 4096
#define NTHREADS 512

// ---------------- smem layout (floats) ----------------
#define LDA      36                  // padded row stride (144 B; 2-phase-minimal LDS.64 banks)
#define ASTRIDE  (128 * LDA)         // 4608 floats per A buffer
#define B_OFF    (2 * ASTRIDE)       // 9216: B buffers start
#define BSTRIDE  (256 * LDA)         // 9216 floats per B buffer
#define SMEM_FLOATS (B_OFF + 2 * BSTRIDE)    // 27648 floats
#define SMEM_TOTAL  (SMEM_FLOATS * 4)        // 110592 B
// epilogue overlays:
#define QS_LD    260                 // qc tile stride (32 x 260 floats in A region, 8320 <= 9216)
#define RED_OFF  B_OFF               // reduction buffer 128 x 9 floats (in B region)

__device__ float g_qc[BATCH * DIM];  // qc[b][d] = query@Wq^T + bq + bref

// ---------------- helpers ----------------
__device__ __forceinline__ uint32_t smem_u32(const void* p) {
    uint32_t a;
    asm("{ .reg .u64 t; cvta.to.shared.u64 t, %1; cvt.u32.u64 %0, t; }" : "=r"(a) : "l"(p));
    return a;
}
__device__ __forceinline__ uint32_t cvt_tf32(float x) {
    uint32_t r;
    asm("cvt.rna.tf32.f32 %0, %1;" : "=r"(r) : "f"(x));
    return r;
}
__device__ __forceinline__ float tanh_fast(float x) {
    float r;
    asm("tanh.approx.f32 %0, %1;" : "=f"(r) : "f"(x));
    return r;
}
__device__ __forceinline__ void cp_async16(uint32_t saddr, const void* gaddr) {
    asm volatile("cp.async.cg.shared.global [%0], [%1], 16;"
                 :: "r"(saddr), "l"(gaddr) : "memory");
}
__device__ __forceinline__ void mma_tf32(float* d, const uint32_t* a, const uint32_t* b) {
    asm volatile(
        "mma.sync.aligned.m16n8k8.row.col.f32.tf32.tf32.f32 "
        "{%0,%1,%2,%3}, {%4,%5,%6,%7}, {%8,%9}, {%0,%1,%2,%3};"
        : "+f"(d[0]), "+f"(d[1]), "+f"(d[2]), "+f"(d[3])
        : "r"(a[0]), "r"(a[1]), "r"(a[2]), "r"(a[3]), "r"(b[0]), "r"(b[1]));
}

// ---------------- kernel 1: qc precompute ----------------
__global__ void __launch_bounds__(256) qc_kernel(const float* __restrict__ query,
                                                 const float* __restrict__ Wq,
                                                 const float* __restrict__ bq,
                                                 const float* __restrict__ bref) {
    const int b = blockIdx.x;
    const int d = threadIdx.x;
    __shared__ float qrow[DIM];
    qrow[d] = query[b * DIM + d];
    __syncthreads();

    const float4* w4 = reinterpret_cast<const float4*>(Wq + d * DIM);
    float acc = 0.0f;
#pragma unroll 8
    for (int e4 = 0; e4 < DIM / 4; e4++) {
        float4 w = w4[e4];
        const float4 q = *reinterpret_cast<const float4*>(qrow + e4 * 4);
        acc = fmaf(w.x, q.x, acc);
        acc = fmaf(w.y, q.y, acc);
        acc = fmaf(w.z, q.z, acc);
        acc = fmaf(w.w, q.w, acc);
    }
    g_qc[b * DIM + d] = acc + bq[d] + bref[d];
}

// ---------------- kernel 2: mma.sync tf32 GEMM + tanh epilogue ----------------
// D[n,d]: n-tile 128 rows (row r -> b = SB+(r&31), k = SK+(r>>5)), d = 256.
// 16 warps: wn = warp>>3 (n 64-half), wd = warp&7 (d 32-slice). Warp tile 64x32.
// k-pair permutation: mma k-cols (t, t+4) <-> physical cols (2t, 2t+1) for BOTH
// operands (GEMM invariant under shared k permutation) -> all fragment reads are LDS.64.
__global__ void __launch_bounds__(NTHREADS, 1) attn_main(const float* __restrict__ enc,
                                                         const float* __restrict__ Wref,
                                                         const float* __restrict__ v,
                                                         float* __restrict__ out) {
    extern __shared__ float sm[];
    const uint32_t sbase = smem_u32(sm);
    const int tid  = threadIdx.x;
    const int lane = tid & 31;
    const int warp = tid >> 5;
    const int g = lane >> 2;          // groupID (row within 8)
    const int t = lane & 3;           // thread-in-group
    const int wn = warp >> 3;         // 0..1
    const int wd = warp & 7;          // 0..7
    const int SB = (blockIdx.x & 7) * 32;
    const int SK = (blockIdx.x >> 3) * 4;

    // ---- cp.async copy mapping (512 threads, 6 x 16B each per chunk) ----
    // A: 128 rows x 8 segs; thread: rows (tid>>3), (tid>>3)+64, seg = tid&7
    // B: 256 rows x 8 segs; thread: rows (tid>>3)+64i (i=0..3), seg = tid&7
    const int rA  = tid >> 3;
    const int seg = tid & 7;
    const int nA0 = (SK + (rA >> 5)) * 256 + SB + (rA & 31);
    const float* gA0 = enc + (size_t)nA0 * DIM + seg * 4;   // row rA
    const float* gA1 = gA0 + (size_t)512 * DIM;             // row rA+64 (n += 512)
    const float* gB0 = Wref + (size_t)rA * DIM + seg * 4;   // rows rA + 64i via offset
    const uint32_t sAb = sbase + (uint32_t)(rA * LDA + seg * 4) * 4u;
    const uint32_t sBb = sbase + (uint32_t)(B_OFF + rA * LDA + seg * 4) * 4u;

    float acc[4][4][4];
#pragma unroll
    for (int m = 0; m < 4; m++)
#pragma unroll
        for (int j = 0; j < 4; j++)
#pragma unroll
            for (int c4 = 0; c4 < 4; c4++) acc[m][j][c4] = 0.0f;

    // prologue: issue chunk 0
    {
        cp_async16(sAb, gA0);
        cp_async16(sAb + 64u * LDA * 4u, gA1);
#pragma unroll
        for (int i = 0; i < 4; i++)
            cp_async16(sBb + (uint32_t)i * 64u * LDA * 4u, gB0 + (size_t)i * 64 * DIM);
        asm volatile("cp.async.commit_group;" ::: "memory");
    }

    for (int c = 0; c < NCHUNK; c++) {
        if (c + 1 < NCHUNK) {   // issue next chunk into other buffer (freed last iter)
            const int k0 = (c + 1) * KC;
            const uint32_t bo = (uint32_t)((c + 1) & 1);
            const uint32_t sa = sAb + bo * (ASTRIDE * 4u);
            const uint32_t sb2 = sBb + bo * (BSTRIDE * 4u);
            cp_async16(sa, gA0 + k0);
            cp_async16(sa + 64u * LDA * 4u, gA1 + k0);
#pragma unroll
            for (int i = 0; i < 4; i++)
                cp_async16(sb2 + (uint32_t)i * 64u * LDA * 4u, gB0 + (size_t)i * 64 * DIM + k0);
            asm volatile("cp.async.commit_group;" ::: "memory");
            asm volatile("cp.async.wait_group 1;" ::: "memory");
        } else {
            asm volatile("cp.async.wait_group 0;" ::: "memory");
        }
        __syncthreads();

        const float* A = sm + (c & 1) * ASTRIDE + (wn * 64 + g) * LDA;
        const float* B = sm + B_OFF + (c & 1) * BSTRIDE + (wd * 32 + g) * LDA;

#pragma unroll
        for (int s = 0; s < 4; s++) {      // 4 k8-steps per 32-chunk
            const int ko = 8 * s + 2 * t;  // physical col pair base
            uint32_t af[4][4], bf[4][2];
#pragma unroll
            for (int m = 0; m < 4; m++) {
                const float2 lo = *reinterpret_cast<const float2*>(A + (16 * m) * LDA + ko);
                const float2 hi = *reinterpret_cast<const float2*>(A + (16 * m + 8) * LDA + ko);
                af[m][0] = cvt_tf32(lo.x);  // mma col t,   row g
                af[m][1] = cvt_tf32(hi.x);  // mma col t,   row g+8
                af[m][2] = cvt_tf32(lo.y);  // mma col t+4, row g
                af[m][3] = cvt_tf32(hi.y);  // mma col t+4, row g+8
            }
#pragma unroll
            for (int j = 0; j < 4; j++) {
                const float2 b = *reinterpret_cast<const float2*>(B + (8 * j) * LDA + ko);
                bf[j][0] = cvt_tf32(b.x);   // mma col t
                bf[j][1] = cvt_tf32(b.y);   // mma col t+4
            }
#pragma unroll
            for (int m = 0; m < 4; m++)
#pragma unroll
                for (int j = 0; j < 4; j++)
                    mma_tf32(acc[m][j], af[m], bf[j]);
        }
        __syncthreads();   // before next iteration's cp.async overwrites this buffer
    }

    // ---- epilogue ----
    // stage qc tile (32 b x 256 d) into smem (overlays A region)
    {
#pragma unroll
        for (int i = 0; i < 4; i++) {
            const int idx = tid + NTHREADS * i;      // 2048 float4s
            const int r = idx >> 6, c4 = idx & 63;
            *reinterpret_cast<float4*>(sm + r * QS_LD + c4 * 4) =
                *reinterpret_cast<const float4*>(g_qc + (size_t)(SB + r) * DIM + c4 * 4);
        }
    }
    __syncthreads();

    float vv[4][2];
#pragma unroll
    for (int j = 0; j < 4; j++) {
        const int d = wd * 32 + 8 * j + 2 * t;
        vv[j][0] = v[d];
        vv[j][1] = v[d + 1];
    }

    float part[4][2];
#pragma unroll
    for (int m = 0; m < 4; m++) {
#pragma unroll
        for (int h = 0; h < 2; h++) {
            const int row = wn * 64 + 16 * m + 8 * h + g;
            const float* q = sm + (row & 31) * QS_LD + wd * 32 + 2 * t;
            float p = 0.0f;
#pragma unroll
            for (int j = 0; j < 4; j++) {
                p = fmaf(vv[j][0], tanh_fast(acc[m][j][2 * h]     + q[8 * j]),     p);
                p = fmaf(vv[j][1], tanh_fast(acc[m][j][2 * h + 1] + q[8 * j + 1]), p);
            }
            // quad (t) reduction: lanes 4g..4g+3 cover this warp's 32 d-columns
            p += __shfl_xor_sync(0xffffffffu, p, 1);
            p += __shfl_xor_sync(0xffffffffu, p, 2);
            part[m][h] = p;
        }
    }

    if (t == 0) {
#pragma unroll
        for (int m = 0; m < 4; m++)
#pragma unroll
            for (int h = 0; h < 2; h++) {
                const int row = wn * 64 + 16 * m + 8 * h + g;
                sm[RED_OFF + row * 9 + wd] = part[m][h];
            }
    }
    __syncthreads();

    if (tid < 128) {
        float u = 0.0f;
#pragma unroll
        for (int r = 0; r < 8; r++) u += sm[RED_OFF + tid * 9 + r];
        out[(size_t)(SB + (tid & 31)) * KSEQ + SK + (tid >> 5)] = 10.0f * tanhf(u);
    }
}

extern "C" void kernel_launch(void* const* d_in, const int* in_sizes, int n_in,
                              void* d_out, int out_size) {
    const float* enc   = (const float*)d_in[0];  // (2048, 256, 256)
    const float* query = (const float*)d_in[1];  // (256, 256)
    const float* Wq    = (const float*)d_in[2];  // (256, 256)
    const float* bq    = (const float*)d_in[3];  // (256,)
    const float* Wref  = (const float*)d_in[4];  // (256, 256)
    const float* bref  = (const float*)d_in[5];  // (256,)
    const float* v     = (const float*)d_in[6];  // (256,)
    float* out = (float*)d_out;                  // (256, 2048)

    cudaFuncSetAttribute(attn_main, cudaFuncAttributeMaxDynamicSharedMemorySize, SMEM_TOTAL);

    qc_kernel<<<BATCH, DIM>>>(query, Wq, bq, bref);
    attn_main<<<GRID, NTHREADS, SMEM_TOTAL>>>(enc, Wref, v, out);
}